// round 7
// baseline (speedup 1.0000x reference)
#include <cuda_runtime.h>
#include <cuda_bf16.h>

// SoftmaxPooling: y[g] = sum_{i in g} exp(Xa[i]) * X[i] / sum_{i in g} exp(Xa[i])
// graph_idx sorted ascending -> segments are contiguous node ranges.
// SINGLE fused kernel: one CTA per graph. Warps 0/1 find [start,end) via a
// warp-parallel 32-ary search (5 memory rounds); then all 4 warps stream the
// segment rows with float4 lanes, unroll 2, __ldcs, smem cross-warp reduce.

#define D 128

__device__ __forceinline__ int warp_search(const int* __restrict__ gidx,
                                           int n_nodes, int target, int l)
{
    // first index i in [0, n_nodes] with gidx[i] >= target (virtual gidx[n]=+inf)
    int lo = 0, hi = n_nodes;              // answer in [lo, hi]
    while (hi - lo > 32) {
        const int range = hi - lo;
        const int p = lo + (int)(((long long)range * l) >> 5);   // lane probe
        const bool b = (gidx[p] < target);
        const unsigned mask = __ballot_sync(0xffffffffu, b);
        if (mask == 0u) { hi = lo; break; }                      // gidx[lo] >= target
        const int k = 31 - __clz(mask);                          // highest lane with b
        const int newlo = lo + (int)(((long long)range * k) >> 5) + 1;
        const int newhi = (k < 31)
            ? lo + (int)(((long long)range * (k + 1)) >> 5)
            : hi;
        lo = newlo; hi = newhi;
    }
    // final round: probe lo..lo+31
    const int p = lo + l;
    const bool b = (p < hi) && (gidx[p] < target);
    return lo + __popc(__ballot_sync(0xffffffffu, b));
}

__global__ __launch_bounds__(128, 12) void softmax_pool_kernel(
    const float* __restrict__ X,
    const float* __restrict__ Xatt,
    const int*   __restrict__ gidx,
    float*       __restrict__ out,
    int n_nodes)
{
    const int g = blockIdx.x;
    const int t = threadIdx.x;
    const int w = t >> 5;          // warp 0..3
    const int l = t & 31;          // lane -> columns [4l, 4l+4)

    __shared__ int s_b[2];
    __shared__ float4 s_a[4][32];
    __shared__ float4 s_w[4][32];

    if (w < 2) {
        const int ans = warp_search(gidx, n_nodes, g + w, l);
        if (l == 0) s_b[w] = ans;
    }
    __syncthreads();

    const int start = s_b[0];
    const int end   = s_b[1];

    float4 aa = {0.f,0.f,0.f,0.f};
    float4 ww = {0.f,0.f,0.f,0.f};

    const float4* pXa = (const float4*)(Xatt) + (size_t)(start + w) * 32 + l;
    const float4* pX  = (const float4*)(X)    + (size_t)(start + w) * 32 + l;

    int i = start + w;
    for (; i + 4 < end; i += 8) {
        float4 xa0 = __ldcs(pXa);
        float4 x0  = __ldcs(pX);
        float4 xa1 = __ldcs(pXa + 128);
        float4 x1  = __ldcs(pX  + 128);
        pXa += 256; pX += 256;

        xa0.x = __expf(xa0.x); xa0.y = __expf(xa0.y); xa0.z = __expf(xa0.z); xa0.w = __expf(xa0.w);
        xa1.x = __expf(xa1.x); xa1.y = __expf(xa1.y); xa1.z = __expf(xa1.z); xa1.w = __expf(xa1.w);

        aa.x += xa0.x; aa.y += xa0.y; aa.z += xa0.z; aa.w += xa0.w;
        ww.x = fmaf(xa0.x, x0.x, ww.x); ww.y = fmaf(xa0.y, x0.y, ww.y);
        ww.z = fmaf(xa0.z, x0.z, ww.z); ww.w = fmaf(xa0.w, x0.w, ww.w);

        aa.x += xa1.x; aa.y += xa1.y; aa.z += xa1.z; aa.w += xa1.w;
        ww.x = fmaf(xa1.x, x1.x, ww.x); ww.y = fmaf(xa1.y, x1.y, ww.y);
        ww.z = fmaf(xa1.z, x1.z, ww.z); ww.w = fmaf(xa1.w, x1.w, ww.w);
    }
    for (; i < end; i += 4) {
        float4 xa = __ldcs(pXa);
        float4 x  = __ldcs(pX);
        pXa += 128; pX += 128;
        xa.x = __expf(xa.x); xa.y = __expf(xa.y); xa.z = __expf(xa.z); xa.w = __expf(xa.w);
        aa.x += xa.x; aa.y += xa.y; aa.z += xa.z; aa.w += xa.w;
        ww.x = fmaf(xa.x, x.x, ww.x); ww.y = fmaf(xa.y, x.y, ww.y);
        ww.z = fmaf(xa.z, x.z, ww.z); ww.w = fmaf(xa.w, x.w, ww.w);
    }

    s_a[w][l] = aa;
    s_w[w][l] = ww;
    __syncthreads();

    if (t < 32) {
        float4 A = s_a[0][t], W = s_w[0][t];
        #pragma unroll
        for (int k = 1; k < 4; ++k) {
            float4 a = s_a[k][t], wv = s_w[k][t];
            A.x += a.x; A.y += a.y; A.z += a.z; A.w += a.w;
            W.x += wv.x; W.y += wv.y; W.z += wv.z; W.w += wv.w;
        }
        float4 r;
        r.x = W.x / A.x; r.y = W.y / A.y; r.z = W.z / A.z; r.w = W.w / A.w;
        ((float4*)(out + (size_t)g * D))[t] = r;
    }
}

extern "C" void kernel_launch(void* const* d_in, const int* in_sizes, int n_in,
                              void* d_out, int out_size)
{
    const float* X    = (const float*)d_in[0];
    const float* Xatt = (const float*)d_in[1];
    const int*   gidx = (const int*)d_in[2];

    const int n_nodes  = in_sizes[2];
    const int n_graphs = in_sizes[3];
    (void)n_in; (void)out_size;

    softmax_pool_kernel<<<n_graphs, D>>>(X, Xatt, gidx, (float*)d_out, n_nodes);
}

// round 9
// speedup vs baseline: 1.0203x; 1.0203x over previous
#include <cuda_runtime.h>
#include <cuda_bf16.h>

// SoftmaxPooling: y[g] = sum_{i in g} exp(Xa[i]) * X[i] / sum_{i in g} exp(Xa[i])
// graph_idx sorted ascending -> segments are contiguous node ranges.
// Pass 1: vectorized boundary kernel (int4): seg_start[g] = first i with gidx[i] >= g.
// Pass 2: one CTA per graph: 4 warps stride rows by 4, float4 lanes, UNROLL 4
//         (8 LDG.128 front-batched per warp iteration), __ldcs, smem reduce.

#define D 128
#define MAX_GRAPHS (4 * 1024 * 1024)

__device__ int g_seg_start[MAX_GRAPHS + 1];

__global__ void boundaries_kernel(const int* __restrict__ gidx,
                                  int n_nodes, int n_graphs)
{
    const int t  = blockIdx.x * blockDim.x + threadIdx.x;
    const int i0 = t << 2;
    if (i0 > n_nodes) return;

    int v[4];
    if (i0 + 3 < n_nodes) {
        int4 q = *(const int4*)(gidx + i0);
        v[0] = q.x; v[1] = q.y; v[2] = q.z; v[3] = q.w;
    } else {
        #pragma unroll
        for (int k = 0; k < 4; ++k)
            v[k] = (i0 + k < n_nodes) ? gidx[i0 + k] : n_graphs;
    }

    int prv = (i0 > 0) ? gidx[i0 - 1] : -1;

    #pragma unroll
    for (int k = 0; k < 4; ++k) {
        const int i = i0 + k;
        if (i > n_nodes) break;
        int cur = v[k];
        if (cur > n_graphs) cur = n_graphs;
        for (int g = prv + 1; g <= cur; ++g)
            g_seg_start[g] = i;
        prv = cur;
    }
}

__device__ __forceinline__ void acc_row(float4 xa, float4 xv,
                                        float4& aa, float4& ww)
{
    xa.x = __expf(xa.x); xa.y = __expf(xa.y);
    xa.z = __expf(xa.z); xa.w = __expf(xa.w);
    aa.x += xa.x; aa.y += xa.y; aa.z += xa.z; aa.w += xa.w;
    ww.x = fmaf(xa.x, xv.x, ww.x); ww.y = fmaf(xa.y, xv.y, ww.y);
    ww.z = fmaf(xa.z, xv.z, ww.z); ww.w = fmaf(xa.w, xv.w, ww.w);
}

__global__ __launch_bounds__(128, 8) void softmax_pool_kernel(
    const float* __restrict__ X,
    const float* __restrict__ Xatt,
    float*       __restrict__ out)
{
    const int g = blockIdx.x;
    const int t = threadIdx.x;
    const int w = t >> 5;          // warp 0..3
    const int l = t & 31;          // lane -> columns [4l, 4l+4)

    const int start = g_seg_start[g];
    const int end   = g_seg_start[g + 1];

    float4 aa = {0.f,0.f,0.f,0.f};
    float4 ww = {0.f,0.f,0.f,0.f};

    // warp w owns rows start+w, start+w+4, ... ; row step 4 -> +128 float4s
    const float4* pXa = (const float4*)(Xatt) + (size_t)(start + w) * 32 + l;
    const float4* pX  = (const float4*)(X)    + (size_t)(start + w) * 32 + l;

    int i = start + w;
    // unroll 4: rows i, i+4, i+8, i+12 -> 8 LDG.128 in flight per warp
    for (; i + 12 < end; i += 16) {
        float4 xa0 = __ldcs(pXa);
        float4 x0  = __ldcs(pX);
        float4 xa1 = __ldcs(pXa + 128);
        float4 x1  = __ldcs(pX  + 128);
        float4 xa2 = __ldcs(pXa + 256);
        float4 x2  = __ldcs(pX  + 256);
        float4 xa3 = __ldcs(pXa + 384);
        float4 x3  = __ldcs(pX  + 384);
        pXa += 512; pX += 512;

        acc_row(xa0, x0, aa, ww);
        acc_row(xa1, x1, aa, ww);
        acc_row(xa2, x2, aa, ww);
        acc_row(xa3, x3, aa, ww);
    }
    for (; i < end; i += 4) {
        float4 xa = __ldcs(pXa);
        float4 xv = __ldcs(pX);
        pXa += 128; pX += 128;
        acc_row(xa, xv, aa, ww);
    }

    __shared__ float4 s_a[4][32];
    __shared__ float4 s_w[4][32];
    s_a[w][l] = aa;
    s_w[w][l] = ww;
    __syncthreads();

    if (t < 32) {
        float4 A = s_a[0][t], W = s_w[0][t];
        #pragma unroll
        for (int k = 1; k < 4; ++k) {
            float4 a = s_a[k][t], wv = s_w[k][t];
            A.x += a.x; A.y += a.y; A.z += a.z; A.w += a.w;
            W.x += wv.x; W.y += wv.y; W.z += wv.z; W.w += wv.w;
        }
        float4 r;
        r.x = W.x / A.x; r.y = W.y / A.y; r.z = W.z / A.z; r.w = W.w / A.w;
        ((float4*)(out + (size_t)g * D))[t] = r;
    }
}

extern "C" void kernel_launch(void* const* d_in, const int* in_sizes, int n_in,
                              void* d_out, int out_size)
{
    const float* X    = (const float*)d_in[0];
    const float* Xatt = (const float*)d_in[1];
    const int*   gidx = (const int*)d_in[2];

    const int n_nodes  = in_sizes[2];
    const int n_graphs = in_sizes[3];
    (void)n_in; (void)out_size;

    int bthreads = 256;
    int work     = (n_nodes >> 2) + 1;
    int bblocks  = (work + bthreads - 1) / bthreads;
    boundaries_kernel<<<bblocks, bthreads>>>(gidx, n_nodes, n_graphs);

    softmax_pool_kernel<<<n_graphs, D>>>(X, Xatt, (float*)d_out);
}

// round 10
// speedup vs baseline: 1.0292x; 1.0087x over previous
#include <cuda_runtime.h>
#include <cuda_bf16.h>

// SoftmaxPooling: y[g] = sum_{i in g} exp(Xa[i]) * X[i] / sum_{i in g} exp(Xa[i])
// graph_idx sorted ascending -> segments are contiguous node ranges.
// Pass 1: vectorized boundary kernel (int4 reads) writes packed int2
//         g_bounds[g] = {start, end} per graph (one LDG.64 in the pool kernel).
// Pass 2: one CTA per graph: 4 warps stride rows by 4, float4 lanes, unroll 2,
//         __ldcs streaming loads, smem cross-warp reduce. (Proven best body.)

#define D 128
#define MAX_GRAPHS (4 * 1024 * 1024)

__device__ int2 g_bounds[MAX_GRAPHS];

__global__ void boundaries_kernel(const int* __restrict__ gidx,
                                  int n_nodes, int n_graphs)
{
    const int t  = blockIdx.x * blockDim.x + threadIdx.x;
    const int i0 = t << 2;
    if (i0 > n_nodes) return;

    int v[4];
    if (i0 + 3 < n_nodes) {
        int4 q = *(const int4*)(gidx + i0);
        v[0] = q.x; v[1] = q.y; v[2] = q.z; v[3] = q.w;
    } else {
        #pragma unroll
        for (int k = 0; k < 4; ++k)
            v[k] = (i0 + k < n_nodes) ? gidx[i0 + k] : n_graphs;
    }

    int prv = (i0 > 0) ? gidx[i0 - 1] : -1;

    #pragma unroll
    for (int k = 0; k < 4; ++k) {
        const int i = i0 + k;
        if (i > n_nodes) break;
        int cur = v[k];
        if (cur > n_graphs) cur = n_graphs;
        // transition prv -> cur at node i:
        //   graphs (prv, cur] start at i; graphs [prv, cur) end at i
        for (int g = prv + 1; g <= cur; ++g) {
            if (g < n_graphs) g_bounds[g].x = i;
            if (g > 0)        g_bounds[g - 1].y = i;
        }
        prv = cur;
    }
}

__global__ __launch_bounds__(128, 12) void softmax_pool_kernel(
    const float* __restrict__ X,
    const float* __restrict__ Xatt,
    float*       __restrict__ out)
{
    const int g = blockIdx.x;
    const int t = threadIdx.x;
    const int w = t >> 5;          // warp 0..3
    const int l = t & 31;          // lane -> columns [4l, 4l+4)

    const int2 b = g_bounds[g];    // one LDG.64
    const int start = b.x;
    const int end   = b.y;

    float4 aa = {0.f,0.f,0.f,0.f};
    float4 ww = {0.f,0.f,0.f,0.f};

    const float4* pXa = (const float4*)(Xatt) + (size_t)(start + w) * 32 + l;
    const float4* pX  = (const float4*)(X)    + (size_t)(start + w) * 32 + l;

    int i = start + w;
    for (; i + 4 < end; i += 8) {
        float4 xa0 = __ldcs(pXa);
        float4 x0  = __ldcs(pX);
        float4 xa1 = __ldcs(pXa + 128);
        float4 x1  = __ldcs(pX  + 128);
        pXa += 256; pX += 256;

        xa0.x = __expf(xa0.x); xa0.y = __expf(xa0.y); xa0.z = __expf(xa0.z); xa0.w = __expf(xa0.w);
        xa1.x = __expf(xa1.x); xa1.y = __expf(xa1.y); xa1.z = __expf(xa1.z); xa1.w = __expf(xa1.w);

        aa.x += xa0.x; aa.y += xa0.y; aa.z += xa0.z; aa.w += xa0.w;
        ww.x = fmaf(xa0.x, x0.x, ww.x); ww.y = fmaf(xa0.y, x0.y, ww.y);
        ww.z = fmaf(xa0.z, x0.z, ww.z); ww.w = fmaf(xa0.w, x0.w, ww.w);

        aa.x += xa1.x; aa.y += xa1.y; aa.z += xa1.z; aa.w += xa1.w;
        ww.x = fmaf(xa1.x, x1.x, ww.x); ww.y = fmaf(xa1.y, x1.y, ww.y);
        ww.z = fmaf(xa1.z, x1.z, ww.z); ww.w = fmaf(xa1.w, x1.w, ww.w);
    }
    for (; i < end; i += 4) {
        float4 xa = __ldcs(pXa);
        float4 x  = __ldcs(pX);
        pXa += 128; pX += 128;
        xa.x = __expf(xa.x); xa.y = __expf(xa.y); xa.z = __expf(xa.z); xa.w = __expf(xa.w);
        aa.x += xa.x; aa.y += xa.y; aa.z += xa.z; aa.w += xa.w;
        ww.x = fmaf(xa.x, x.x, ww.x); ww.y = fmaf(xa.y, x.y, ww.y);
        ww.z = fmaf(xa.z, x.z, ww.z); ww.w = fmaf(xa.w, x.w, ww.w);
    }

    __shared__ float4 s_a[4][32];
    __shared__ float4 s_w[4][32];
    s_a[w][l] = aa;
    s_w[w][l] = ww;
    __syncthreads();

    if (t < 32) {
        float4 A = s_a[0][t], W = s_w[0][t];
        #pragma unroll
        for (int k = 1; k < 4; ++k) {
            float4 a = s_a[k][t], wv = s_w[k][t];
            A.x += a.x; A.y += a.y; A.z += a.z; A.w += a.w;
            W.x += wv.x; W.y += wv.y; W.z += wv.z; W.w += wv.w;
        }
        float4 r;
        r.x = W.x / A.x; r.y = W.y / A.y; r.z = W.z / A.z; r.w = W.w / A.w;
        ((float4*)(out + (size_t)g * D))[t] = r;
    }
}

extern "C" void kernel_launch(void* const* d_in, const int* in_sizes, int n_in,
                              void* d_out, int out_size)
{
    const float* X    = (const float*)d_in[0];
    const float* Xatt = (const float*)d_in[1];
    const int*   gidx = (const int*)d_in[2];

    const int n_nodes  = in_sizes[2];
    const int n_graphs = in_sizes[3];
    (void)n_in; (void)out_size;

    int bthreads = 256;
    int work     = (n_nodes >> 2) + 1;
    int bblocks  = (work + bthreads - 1) / bthreads;
    boundaries_kernel<<<bblocks, bthreads>>>(gidx, n_nodes, n_graphs);

    softmax_pool_kernel<<<n_graphs, D>>>(X, Xatt, (float*)d_out);
}

// round 11
// speedup vs baseline: 1.0301x; 1.0009x over previous
#include <cuda_runtime.h>
#include <cuda_bf16.h>

// SoftmaxPooling: y[g] = sum_{i in g} exp(Xa[i]) * X[i] / sum_{i in g} exp(Xa[i])
// graph_idx sorted ascending -> segments are contiguous node ranges.
// Pass 1: vectorized boundary kernel (int4 reads) writes packed int2
//         g_bounds[g] = {start, end} per graph (one LDG.64 in the pool kernel).
// Pass 2: one CTA per graph: 4 warps stride rows by 4, float4 lanes, unroll 2,
//         __ldcs streaming loads, smem cross-warp reduce, __stcs output store.
// Converged config: measured 147.0 us ~= 1.038 GB / 7.03 TB/s (HBM roofline).

#define D 128
#define MAX_GRAPHS (4 * 1024 * 1024)

__device__ int2 g_bounds[MAX_GRAPHS];

__global__ void boundaries_kernel(const int* __restrict__ gidx,
                                  int n_nodes, int n_graphs)
{
    const int t  = blockIdx.x * blockDim.x + threadIdx.x;
    const int i0 = t << 2;
    if (i0 > n_nodes) return;

    int v[4];
    if (i0 + 3 < n_nodes) {
        int4 q = *(const int4*)(gidx + i0);
        v[0] = q.x; v[1] = q.y; v[2] = q.z; v[3] = q.w;
    } else {
        #pragma unroll
        for (int k = 0; k < 4; ++k)
            v[k] = (i0 + k < n_nodes) ? gidx[i0 + k] : n_graphs;
    }

    int prv = (i0 > 0) ? gidx[i0 - 1] : -1;

    #pragma unroll
    for (int k = 0; k < 4; ++k) {
        const int i = i0 + k;
        if (i > n_nodes) break;
        int cur = v[k];
        if (cur > n_graphs) cur = n_graphs;
        // transition prv -> cur at node i:
        //   graphs (prv, cur] start at i; graphs [prv, cur) end at i
        for (int g = prv + 1; g <= cur; ++g) {
            if (g < n_graphs) g_bounds[g].x = i;
            if (g > 0)        g_bounds[g - 1].y = i;
        }
        prv = cur;
    }
}

__global__ __launch_bounds__(128, 12) void softmax_pool_kernel(
    const float* __restrict__ X,
    const float* __restrict__ Xatt,
    float*       __restrict__ out)
{
    const int g = blockIdx.x;
    const int t = threadIdx.x;
    const int w = t >> 5;          // warp 0..3
    const int l = t & 31;          // lane -> columns [4l, 4l+4)

    const int2 b = g_bounds[g];    // one LDG.64
    const int start = b.x;
    const int end   = b.y;

    float4 aa = {0.f,0.f,0.f,0.f};
    float4 ww = {0.f,0.f,0.f,0.f};

    const float4* pXa = (const float4*)(Xatt) + (size_t)(start + w) * 32 + l;
    const float4* pX  = (const float4*)(X)    + (size_t)(start + w) * 32 + l;

    int i = start + w;
    for (; i + 4 < end; i += 8) {
        float4 xa0 = __ldcs(pXa);
        float4 x0  = __ldcs(pX);
        float4 xa1 = __ldcs(pXa + 128);
        float4 x1  = __ldcs(pX  + 128);
        pXa += 256; pX += 256;

        xa0.x = __expf(xa0.x); xa0.y = __expf(xa0.y); xa0.z = __expf(xa0.z); xa0.w = __expf(xa0.w);
        xa1.x = __expf(xa1.x); xa1.y = __expf(xa1.y); xa1.z = __expf(xa1.z); xa1.w = __expf(xa1.w);

        aa.x += xa0.x; aa.y += xa0.y; aa.z += xa0.z; aa.w += xa0.w;
        ww.x = fmaf(xa0.x, x0.x, ww.x); ww.y = fmaf(xa0.y, x0.y, ww.y);
        ww.z = fmaf(xa0.z, x0.z, ww.z); ww.w = fmaf(xa0.w, x0.w, ww.w);

        aa.x += xa1.x; aa.y += xa1.y; aa.z += xa1.z; aa.w += xa1.w;
        ww.x = fmaf(xa1.x, x1.x, ww.x); ww.y = fmaf(xa1.y, x1.y, ww.y);
        ww.z = fmaf(xa1.z, x1.z, ww.z); ww.w = fmaf(xa1.w, x1.w, ww.w);
    }
    for (; i < end; i += 4) {
        float4 xa = __ldcs(pXa);
        float4 x  = __ldcs(pX);
        pXa += 128; pX += 128;
        xa.x = __expf(xa.x); xa.y = __expf(xa.y); xa.z = __expf(xa.z); xa.w = __expf(xa.w);
        aa.x += xa.x; aa.y += xa.y; aa.z += xa.z; aa.w += xa.w;
        ww.x = fmaf(xa.x, x.x, ww.x); ww.y = fmaf(xa.y, x.y, ww.y);
        ww.z = fmaf(xa.z, x.z, ww.z); ww.w = fmaf(xa.w, x.w, ww.w);
    }

    __shared__ float4 s_a[4][32];
    __shared__ float4 s_w[4][32];
    s_a[w][l] = aa;
    s_w[w][l] = ww;
    __syncthreads();

    if (t < 32) {
        float4 A = s_a[0][t], W = s_w[0][t];
        #pragma unroll
        for (int k = 1; k < 4; ++k) {
            float4 a = s_a[k][t], wv = s_w[k][t];
            A.x += a.x; A.y += a.y; A.z += a.z; A.w += a.w;
            W.x += wv.x; W.y += wv.y; W.z += wv.z; W.w += wv.w;
        }
        float4 r;
        r.x = W.x / A.x; r.y = W.y / A.y; r.z = W.z / A.z; r.w = W.w / A.w;
        __stcs(((float4*)(out + (size_t)g * D)) + t, r);   // streaming store
    }
}

extern "C" void kernel_launch(void* const* d_in, const int* in_sizes, int n_in,
                              void* d_out, int out_size)
{
    const float* X    = (const float*)d_in[0];
    const float* Xatt = (const float*)d_in[1];
    const int*   gidx = (const int*)d_in[2];

    const int n_nodes  = in_sizes[2];
    const int n_graphs = in_sizes[3];
    (void)n_in; (void)out_size;

    int bthreads = 256;
    int work     = (n_nodes >> 2) + 1;
    int bblocks  = (work + bthreads - 1) / bthreads;
    boundaries_kernel<<<bblocks, bthreads>>>(gidx, n_nodes, n_graphs);

    softmax_pool_kernel<<<n_graphs, D>>>(X, Xatt, (float*)d_out);
}

// round 12
// speedup vs baseline: 1.0495x; 1.0189x over previous
#include <cuda_runtime.h>
#include <cuda_bf16.h>

// SoftmaxPooling: y[g] = sum_{i in g} exp(Xa[i]) * X[i] / sum_{i in g} exp(Xa[i])
// graph_idx sorted ascending -> segments are contiguous node ranges.
// Pass 1: vectorized boundary kernel (int4 reads) writes packed int2
//         g_bounds[g] = {start, end} per graph (one LDG.64 in the pool kernel).
// Pass 2: one CTA per graph: 4 warps stride rows by 4, float4 lanes, unroll 2,
//         __ldcs streaming loads, smem cross-warp reduce, plain output store.
// FINAL converged config: 146.75 us kernel / 88.7% DRAM = 1.038 GB @ 7.03 TB/s,
// the measured HBM3e streaming roofline on this part.

#define D 128
#define MAX_GRAPHS (4 * 1024 * 1024)

__device__ int2 g_bounds[MAX_GRAPHS];

__global__ void boundaries_kernel(const int* __restrict__ gidx,
                                  int n_nodes, int n_graphs)
{
    const int t  = blockIdx.x * blockDim.x + threadIdx.x;
    const int i0 = t << 2;
    if (i0 > n_nodes) return;

    int v[4];
    if (i0 + 3 < n_nodes) {
        int4 q = *(const int4*)(gidx + i0);
        v[0] = q.x; v[1] = q.y; v[2] = q.z; v[3] = q.w;
    } else {
        #pragma unroll
        for (int k = 0; k < 4; ++k)
            v[k] = (i0 + k < n_nodes) ? gidx[i0 + k] : n_graphs;
    }

    int prv = (i0 > 0) ? gidx[i0 - 1] : -1;

    #pragma unroll
    for (int k = 0; k < 4; ++k) {
        const int i = i0 + k;
        if (i > n_nodes) break;
        int cur = v[k];
        if (cur > n_graphs) cur = n_graphs;
        // transition prv -> cur at node i:
        //   graphs (prv, cur] start at i; graphs [prv, cur) end at i
        for (int g = prv + 1; g <= cur; ++g) {
            if (g < n_graphs) g_bounds[g].x = i;
            if (g > 0)        g_bounds[g - 1].y = i;
        }
        prv = cur;
    }
}

__global__ __launch_bounds__(128, 12) void softmax_pool_kernel(
    const float* __restrict__ X,
    const float* __restrict__ Xatt,
    float*       __restrict__ out)
{
    const int g = blockIdx.x;
    const int t = threadIdx.x;
    const int w = t >> 5;          // warp 0..3
    const int l = t & 31;          // lane -> columns [4l, 4l+4)

    const int2 b = g_bounds[g];    // one LDG.64
    const int start = b.x;
    const int end   = b.y;

    float4 aa = {0.f,0.f,0.f,0.f};
    float4 ww = {0.f,0.f,0.f,0.f};

    const float4* pXa = (const float4*)(Xatt) + (size_t)(start + w) * 32 + l;
    const float4* pX  = (const float4*)(X)    + (size_t)(start + w) * 32 + l;

    int i = start + w;
    for (; i + 4 < end; i += 8) {
        float4 xa0 = __ldcs(pXa);
        float4 x0  = __ldcs(pX);
        float4 xa1 = __ldcs(pXa + 128);
        float4 x1  = __ldcs(pX  + 128);
        pXa += 256; pX += 256;

        xa0.x = __expf(xa0.x); xa0.y = __expf(xa0.y); xa0.z = __expf(xa0.z); xa0.w = __expf(xa0.w);
        xa1.x = __expf(xa1.x); xa1.y = __expf(xa1.y); xa1.z = __expf(xa1.z); xa1.w = __expf(xa1.w);

        aa.x += xa0.x; aa.y += xa0.y; aa.z += xa0.z; aa.w += xa0.w;
        ww.x = fmaf(xa0.x, x0.x, ww.x); ww.y = fmaf(xa0.y, x0.y, ww.y);
        ww.z = fmaf(xa0.z, x0.z, ww.z); ww.w = fmaf(xa0.w, x0.w, ww.w);

        aa.x += xa1.x; aa.y += xa1.y; aa.z += xa1.z; aa.w += xa1.w;
        ww.x = fmaf(xa1.x, x1.x, ww.x); ww.y = fmaf(xa1.y, x1.y, ww.y);
        ww.z = fmaf(xa1.z, x1.z, ww.z); ww.w = fmaf(xa1.w, x1.w, ww.w);
    }
    for (; i < end; i += 4) {
        float4 xa = __ldcs(pXa);
        float4 x  = __ldcs(pX);
        pXa += 128; pX += 128;
        xa.x = __expf(xa.x); xa.y = __expf(xa.y); xa.z = __expf(xa.z); xa.w = __expf(xa.w);
        aa.x += xa.x; aa.y += xa.y; aa.z += xa.z; aa.w += xa.w;
        ww.x = fmaf(xa.x, x.x, ww.x); ww.y = fmaf(xa.y, x.y, ww.y);
        ww.z = fmaf(xa.z, x.z, ww.z); ww.w = fmaf(xa.w, x.w, ww.w);
    }

    __shared__ float4 s_a[4][32];
    __shared__ float4 s_w[4][32];
    s_a[w][l] = aa;
    s_w[w][l] = ww;
    __syncthreads();

    if (t < 32) {
        float4 A = s_a[0][t], W = s_w[0][t];
        #pragma unroll
        for (int k = 1; k < 4; ++k) {
            float4 a = s_a[k][t], wv = s_w[k][t];
            A.x += a.x; A.y += a.y; A.z += a.z; A.w += a.w;
            W.x += wv.x; W.y += wv.y; W.z += wv.z; W.w += wv.w;
        }
        float4 r;
        r.x = W.x / A.x; r.y = W.y / A.y; r.z = W.z / A.z; r.w = W.w / A.w;
        ((float4*)(out + (size_t)g * D))[t] = r;
    }
}

extern "C" void kernel_launch(void* const* d_in, const int* in_sizes, int n_in,
                              void* d_out, int out_size)
{
    const float* X    = (const float*)d_in[0];
    const float* Xatt = (const float*)d_in[1];
    const int*   gidx = (const int*)d_in[2];

    const int n_nodes  = in_sizes[2];
    const int n_graphs = in_sizes[3];
    (void)n_in; (void)out_size;

    int bthreads = 256;
    int work     = (n_nodes >> 2) + 1;
    int bblocks  = (work + bthreads - 1) / bthreads;
    boundaries_kernel<<<bblocks, bthreads>>>(gidx, n_nodes, n_graphs);

    softmax_pool_kernel<<<n_graphs, D>>>(X, Xatt, (float*)d_out);
}

// round 13
// speedup vs baseline: 1.0516x; 1.0020x over previous
#include <cuda_runtime.h>
#include <cuda_bf16.h>

// SoftmaxPooling: y[g] = sum_{i in g} exp(Xa[i]) * X[i] / sum_{i in g} exp(Xa[i])
// graph_idx sorted ascending -> segments are contiguous node ranges.
// Pass 1: vectorized boundary kernel (int4 reads) writes packed int2
//         g_bounds[g] = {start, end} per graph (one LDG.64 in the pool kernel).
// Pass 2: one CTA per graph: 4 warps stride rows by 4, float4 lanes, unroll 2,
//         __ldcs streaming loads, smem cross-warp reduce, plain output store.
// FINAL converged config: 144.2-147.0 us run envelope, 88-90% DRAM
// (1.038 GB at ~7.1 TB/s sustained = the HBM3e streaming ceiling on this part).
// All alternatives tested and rejected: persistent grid (-19%), warp-per-graph
// (-7%), fused in-kernel search (-3%), unroll-4 (-1%), occupancy 48-73% (flat),
// __stcs stores (neutral/negative).

#define D 128
#define MAX_GRAPHS (4 * 1024 * 1024)

__device__ int2 g_bounds[MAX_GRAPHS];

__global__ void boundaries_kernel(const int* __restrict__ gidx,
                                  int n_nodes, int n_graphs)
{
    const int t  = blockIdx.x * blockDim.x + threadIdx.x;
    const int i0 = t << 2;
    if (i0 > n_nodes) return;

    int v[4];
    if (i0 + 3 < n_nodes) {
        int4 q = *(const int4*)(gidx + i0);
        v[0] = q.x; v[1] = q.y; v[2] = q.z; v[3] = q.w;
    } else {
        #pragma unroll
        for (int k = 0; k < 4; ++k)
            v[k] = (i0 + k < n_nodes) ? gidx[i0 + k] : n_graphs;
    }

    int prv = (i0 > 0) ? gidx[i0 - 1] : -1;

    #pragma unroll
    for (int k = 0; k < 4; ++k) {
        const int i = i0 + k;
        if (i > n_nodes) break;
        int cur = v[k];
        if (cur > n_graphs) cur = n_graphs;
        // transition prv -> cur at node i:
        //   graphs (prv, cur] start at i; graphs [prv, cur) end at i
        for (int g = prv + 1; g <= cur; ++g) {
            if (g < n_graphs) g_bounds[g].x = i;
            if (g > 0)        g_bounds[g - 1].y = i;
        }
        prv = cur;
    }
}

__global__ __launch_bounds__(128, 12) void softmax_pool_kernel(
    const float* __restrict__ X,
    const float* __restrict__ Xatt,
    float*       __restrict__ out)
{
    const int g = blockIdx.x;
    const int t = threadIdx.x;
    const int w = t >> 5;          // warp 0..3
    const int l = t & 31;          // lane -> columns [4l, 4l+4)

    const int2 b = g_bounds[g];    // one LDG.64
    const int start = b.x;
    const int end   = b.y;

    float4 aa = {0.f,0.f,0.f,0.f};
    float4 ww = {0.f,0.f,0.f,0.f};

    const float4* pXa = (const float4*)(Xatt) + (size_t)(start + w) * 32 + l;
    const float4* pX  = (const float4*)(X)    + (size_t)(start + w) * 32 + l;

    int i = start + w;
    for (; i + 4 < end; i += 8) {
        float4 xa0 = __ldcs(pXa);
        float4 x0  = __ldcs(pX);
        float4 xa1 = __ldcs(pXa + 128);
        float4 x1  = __ldcs(pX  + 128);
        pXa += 256; pX += 256;

        xa0.x = __expf(xa0.x); xa0.y = __expf(xa0.y); xa0.z = __expf(xa0.z); xa0.w = __expf(xa0.w);
        xa1.x = __expf(xa1.x); xa1.y = __expf(xa1.y); xa1.z = __expf(xa1.z); xa1.w = __expf(xa1.w);

        aa.x += xa0.x; aa.y += xa0.y; aa.z += xa0.z; aa.w += xa0.w;
        ww.x = fmaf(xa0.x, x0.x, ww.x); ww.y = fmaf(xa0.y, x0.y, ww.y);
        ww.z = fmaf(xa0.z, x0.z, ww.z); ww.w = fmaf(xa0.w, x0.w, ww.w);

        aa.x += xa1.x; aa.y += xa1.y; aa.z += xa1.z; aa.w += xa1.w;
        ww.x = fmaf(xa1.x, x1.x, ww.x); ww.y = fmaf(xa1.y, x1.y, ww.y);
        ww.z = fmaf(xa1.z, x1.z, ww.z); ww.w = fmaf(xa1.w, x1.w, ww.w);
    }
    for (; i < end; i += 4) {
        float4 xa = __ldcs(pXa);
        float4 x  = __ldcs(pX);
        pXa += 128; pX += 128;
        xa.x = __expf(xa.x); xa.y = __expf(xa.y); xa.z = __expf(xa.z); xa.w = __expf(xa.w);
        aa.x += xa.x; aa.y += xa.y; aa.z += xa.z; aa.w += xa.w;
        ww.x = fmaf(xa.x, x.x, ww.x); ww.y = fmaf(xa.y, x.y, ww.y);
        ww.z = fmaf(xa.z, x.z, ww.z); ww.w = fmaf(xa.w, x.w, ww.w);
    }

    __shared__ float4 s_a[4][32];
    __shared__ float4 s_w[4][32];
    s_a[w][l] = aa;
    s_w[w][l] = ww;
    __syncthreads();

    if (t < 32) {
        float4 A = s_a[0][t], W = s_w[0][t];
        #pragma unroll
        for (int k = 1; k < 4; ++k) {
            float4 a = s_a[k][t], wv = s_w[k][t];
            A.x += a.x; A.y += a.y; A.z += a.z; A.w += a.w;
            W.x += wv.x; W.y += wv.y; W.z += wv.z; W.w += wv.w;
        }
        float4 r;
        r.x = W.x / A.x; r.y = W.y / A.y; r.z = W.z / A.z; r.w = W.w / A.w;
        ((float4*)(out + (size_t)g * D))[t] = r;
    }
}

extern "C" void kernel_launch(void* const* d_in, const int* in_sizes, int n_in,
                              void* d_out, int out_size)
{
    const float* X    = (const float*)d_in[0];
    const float* Xatt = (const float*)d_in[1];
    const int*   gidx = (const int*)d_in[2];

    const int n_nodes  = in_sizes[2];
    const int n_graphs = in_sizes[3];
    (void)n_in; (void)out_size;

    int bthreads = 256;
    int work     = (n_nodes >> 2) + 1;
    int bblocks  = (work + bthreads - 1) / bthreads;
    boundaries_kernel<<<bblocks, bthreads>>>(gidx, n_nodes, n_graphs);

    softmax_pool_kernel<<<n_graphs, D>>>(X, Xatt, (float*)d_out);
}